// round 16
// baseline (speedup 1.0000x reference)
#include <cuda_runtime.h>
#include <cuda_fp16.h>
#include <mma.h>
#include <math.h>

using namespace nvcuda;

// Problem constants
#define BATCH 8
#define SEQ   1024
#define DMODEL 1024
#define NHEAD 16
#define HDIM  64
#define BHN   (BATCH*NHEAD)         // 128
#define ROWS  (BATCH*SEQ)           // 8192

// -------- static device scratch --------
__device__ __half g_Wqkvh[1024*3072];          // packed [D, 3*D]
__device__ float  g_bqkv[3072];
__device__ __half g_xh[(size_t)ROWS*DMODEL];
__device__ __half g_Woh[1024*1024];
__device__ __half g_Qh[(size_t)BHN*SEQ*HDIM];  // [bh][s][e]
__device__ __half g_Kh[(size_t)BHN*SEQ*HDIM];  // [bh][s][e]
__device__ __half g_Vh[(size_t)BHN*SEQ*HDIM];  // [bh][e][s]  (TRANSPOSED)
__device__ __half g_ctxh[(size_t)ROWS*DMODEL]; // [b*S+s][h*64+e]
__device__ int    g_mask_i32;

// cp.async helpers (16B)
__device__ __forceinline__ void cp_async16(void* smem, const void* gmem) {
    unsigned s = (unsigned)__cvta_generic_to_shared(smem);
    asm volatile("cp.async.cg.shared.global [%0], [%1], 16;" :: "r"(s), "l"(gmem));
}
__device__ __forceinline__ void cp_commit() { asm volatile("cp.async.commit_group;"); }
__device__ __forceinline__ void cp_wait0()  { asm volatile("cp.async.wait_group 0;"); }

// fp16 mma m16n8k16, fp32 accumulate (documented PTX fragment layouts)
#define MMA16816(d, a0, a1, a2, a3, b0, b1)                                    \
    asm volatile("mma.sync.aligned.m16n8k16.row.col.f32.f16.f16.f32 "          \
                 "{%0,%1,%2,%3}, {%4,%5,%6,%7}, {%8,%9}, {%0,%1,%2,%3};"       \
                 : "+f"(d[0]), "+f"(d[1]), "+f"(d[2]), "+f"(d[3])              \
                 : "r"(a0), "r"(a1), "r"(a2), "r"(a3), "r"(b0), "r"(b1))

// -------- mask dtype detection --------
__global__ void detect_mask_kernel(const int* __restrict__ m) {
    __shared__ int bad;
    if (threadIdx.x == 0) bad = 0;
    __syncthreads();
    int ok = 1;
    for (int i = threadIdx.x; i < 4096; i += 256) {
        int v = m[i];
        if (v != 0 && v != 1) ok = 0;
    }
    if (!ok) atomicOr(&bad, 1);
    __syncthreads();
    if (threadIdx.x == 0) g_mask_i32 = bad ? 0 : 1;
}

// -------- fp16 conversion (dest chosen on-device) --------
__global__ void cvt_half_kernel(const float* __restrict__ in, int which, int n8) {
    __half* out = which ? g_Woh : g_xh;
    int i = blockIdx.x * 256 + threadIdx.x;
    if (i < n8) {
        float4 a = ((const float4*)in)[2 * i];
        float4 b = ((const float4*)in)[2 * i + 1];
        __half2* o = (__half2*)out + 4 * (size_t)i;
        o[0] = __floats2half2_rn(a.x, a.y);
        o[1] = __floats2half2_rn(a.z, a.w);
        o[2] = __floats2half2_rn(b.x, b.y);
        o[3] = __floats2half2_rn(b.z, b.w);
    }
}

// -------- repack weights (half), biases --------
__global__ void repack_kernel(const float* __restrict__ Wq, const float* __restrict__ bq,
                              const float* __restrict__ Wk, const float* __restrict__ bk,
                              const float* __restrict__ Wv, const float* __restrict__ bv) {
    int idx = blockIdx.x * 256 + threadIdx.x;
    if (idx < 3 * 1048576) {
        int sel = idx >> 20;
        int r   = idx & 1048575;
        int h = r >> 16;
        int r2 = r & 65535;
        int d = r2 >> 6;
        int e = r2 & 63;
        const float* W = (sel == 0) ? Wq : (sel == 1 ? Wk : Wv);
        g_Wqkvh[(size_t)d * 3072 + (sel << 10) + (h << 6) + e] =
            __float2half_rn(W[(h << 16) + (d << 6) + e]);
    }
    if (idx < 3072) {
        int sel = idx >> 10;
        int jj = idx & 1023;
        const float* bb = (sel == 0) ? bq : (sel == 1 ? bk : bv);
        g_bqkv[idx] = bb[jj];
    }
}

// -------- fp16 WMMA GEMM: 128x128 block, BK=64, cp.async 2-stage -------------
// Halved barrier count vs BK=32; 32 m16n16k16 per warp per barrier.
#define GA_P 72                        // A pitch (halves), 64 data + 8 pad
#define GB_P 136                       // B pitch (halves)
#define G_AS (128*GA_P)                // 9216 halves
#define G_BS (64*GB_P)                 // 8704 halves
#define G_STAGE (G_AS+G_BS)            // 17920 halves = 35840 B
#define G_BIAS_BYTE (2*G_STAGE*2)      // 71680
#define G_SMEM_BYTES (G_BIAS_BYTE + 16*GB_P*4)   // +8704 = 80384 B

__global__ __launch_bounds__(256, 2) void gemm_h(const float* __restrict__ biasext,
                                                 float* __restrict__ Cext,
                                                 int N, int mode) {
    extern __shared__ char smc[];
    __half* st0 = (__half*)smc;
    float* Bias = (float*)(smc + G_BIAS_BYTE);

    const __half* A = (mode == 0) ? g_xh : g_ctxh;
    const __half* B = (mode == 0) ? g_Wqkvh : g_Woh;
    const float* bias = (mode == 0) ? g_bqkv : biasext;

    int tid = threadIdx.x;
    int warp = tid >> 5;
    int lane = tid & 31;
    int wm = warp >> 1;
    int wn = warp & 1;
    int row0 = blockIdx.y * 128, col0 = blockIdx.x * 128;

    for (int i = tid; i < 16 * 128; i += 256) {
        int r = i >> 7, c = i & 127;
        Bias[r * GB_P + c] = bias[col0 + c];
    }

    // prologue: stage 0 (A 128x64, B 64x128)
    {
        __half* As = st0;
        __half* Bs = st0 + G_AS;
#pragma unroll
        for (int l = 0; l < 4; l++) {
            int i = tid + l * 256;
            int r = i >> 3, c = (i & 7) * 8;                 // A rows 0..127
            cp_async16(&As[r * GA_P + c], A + (size_t)(row0 + r) * 1024 + c);
            int rB = i >> 4, cB = (i & 15) * 8;              // B rows 0..63
            cp_async16(&Bs[rB * GB_P + cB], B + (size_t)rB * N + col0 + cB);
        }
        cp_commit();
    }
    __syncthreads();

    wmma::fragment<wmma::accumulator, 16, 16, 16, float> acc[2][4];
#pragma unroll
    for (int mi = 0; mi < 2; mi++)
#pragma unroll
        for (int ni = 0; ni < 4; ni++)
            wmma::load_matrix_sync(acc[mi][ni], &Bias[wn * 64 + ni * 16], GB_P,
                                   wmma::mem_row_major);

    for (int it = 0; it < 16; ++it) {
        cp_wait0();
        __syncthreads();

        if (it + 1 < 16) {
            int k0 = (it + 1) * 64;
            __half* As2 = st0 + ((it + 1) & 1) * G_STAGE;
            __half* Bs2 = As2 + G_AS;
#pragma unroll
            for (int l = 0; l < 4; l++) {
                int i = tid + l * 256;
                int r = i >> 3, c = (i & 7) * 8;
                cp_async16(&As2[r * GA_P + c], A + (size_t)(row0 + r) * 1024 + k0 + c);
                int rB = i >> 4, cB = (i & 15) * 8;
                cp_async16(&Bs2[rB * GB_P + cB], B + (size_t)(k0 + rB) * N + col0 + cB);
            }
            cp_commit();
        }

        const __half* As = st0 + (it & 1) * G_STAGE;
        const __half* Bs = As + G_AS;
#pragma unroll
        for (int kk = 0; kk < 64; kk += 16) {
            wmma::fragment<wmma::matrix_a, 16, 16, 16, __half, wmma::row_major> af[2];
            wmma::fragment<wmma::matrix_b, 16, 16, 16, __half, wmma::row_major> bf[4];
#pragma unroll
            for (int mi = 0; mi < 2; mi++)
                wmma::load_matrix_sync(af[mi], &As[(wm * 32 + mi * 16) * GA_P + kk], GA_P);
#pragma unroll
            for (int ni = 0; ni < 4; ni++)
                wmma::load_matrix_sync(bf[ni], &Bs[kk * GB_P + wn * 64 + ni * 16], GB_P);
#pragma unroll
            for (int mi = 0; mi < 2; mi++)
#pragma unroll
                for (int ni = 0; ni < 4; ni++)
                    wmma::mma_sync(acc[mi][ni], af[mi], bf[ni], acc[mi][ni]);
        }
    }

    if (mode == 0) {
        __syncthreads();
        float* stg = (float*)smc + warp * 256;
        int sel = col0 >> 10;
        if (sel < 2) {
            __half* dst = (sel == 0) ? g_Qh : g_Kh;
#pragma unroll
            for (int mi = 0; mi < 2; mi++) {
#pragma unroll
                for (int ni = 0; ni < 4; ni++) {
                    wmma::store_matrix_sync(stg, acc[mi][ni], 16, wmma::mem_row_major);
                    __syncwarp();
                    int row = lane >> 1, ch = (lane & 1) * 8;
                    const float* src = stg + row * 16 + ch;
                    __align__(16) __half hh[8];
#pragma unroll
                    for (int t = 0; t < 8; t++) hh[t] = __float2half_rn(src[t]);
                    int r = row0 + wm * 32 + mi * 16 + row;
                    int s = r & 1023, bb = r >> 10;
                    int c = col0 + wn * 64 + ni * 16 + ch;
                    int jj = c & 1023;
                    int hd = jj >> 6, e = jj & 63;
                    *(uint4*)&dst[(((size_t)((bb << 4) + hd)) << 16) + ((size_t)s << 6) + e] =
                        *(uint4*)hh;
                    __syncwarp();
                }
            }
        } else {
            // V: write transposed [bh][e][s]
#pragma unroll
            for (int mi = 0; mi < 2; mi++) {
#pragma unroll
                for (int ni = 0; ni < 4; ni++) {
                    wmma::store_matrix_sync(stg, acc[mi][ni], 16, wmma::mem_row_major);
                    __syncwarp();
                    int e_l = lane >> 1;            // 0..15 (col of tile)
                    int s_off = (lane & 1) * 8;     // 0 or 8 (row block)
                    __align__(16) __half hh[8];
#pragma unroll
                    for (int i = 0; i < 8; i++)
                        hh[i] = __float2half_rn(stg[(s_off + i) * 16 + e_l]);
                    int r = row0 + wm * 32 + mi * 16 + s_off;
                    int s0 = r & 1023, bb = r >> 10;
                    int c = col0 + wn * 64 + ni * 16 + e_l;
                    int jj = c & 1023;
                    int hd = jj >> 6, e = jj & 63;
                    *(uint4*)&g_Vh[(((size_t)((bb << 4) + hd)) * 64 + e) * 1024 + s0] =
                        *(uint4*)hh;
                    __syncwarp();
                }
            }
        }
    } else {
#pragma unroll
        for (int mi = 0; mi < 2; mi++) {
            int r = row0 + wm * 32 + mi * 16;
#pragma unroll
            for (int ni = 0; ni < 4; ni++) {
                int c = col0 + wn * 64 + ni * 16;
                wmma::store_matrix_sync(&Cext[(size_t)r * N + c], acc[mi][ni], N,
                                        wmma::mem_row_major);
            }
        }
    }
}

// -------- flash attention: register-resident FMHA (raw m16n8k16) -------------
// (unchanged from R15: warp owns 16 rows; S, P, O in registers; one
// syncthreads per KV tile; K/Vt/mask cp.async double-buffered.)
#define FP 72
#define FL_K_BYTES (64*FP*2)                       // 9216
#define FL_STAGE_BYTES (2*FL_K_BYTES + 128*64)     // K+Vt+mask = 26624
#define FL_Q_OFF (2*FL_STAGE_BYTES)                // 53248
#define FL_BYTES (FL_Q_OFF + 128*FP*2)             // 71680

__global__ __launch_bounds__(256, 2) void flash_kernel(const unsigned char* __restrict__ m8,
                                                       const int* __restrict__ m32) {
    extern __shared__ char smc[];
    __half* Qs = (__half*)(smc + FL_Q_OFF);

    int tid = threadIdx.x;
    int warp = tid >> 5;
    int lane = tid & 31;
    int gid = lane >> 2;        // 0..7
    int tq = lane & 3;          // 0..3
    int bh = blockIdx.y;
    int b = bh >> 4, h = bh & 15;
    int sq0 = blockIdx.x * 128;
    int rw0 = warp * 16;

    const __half* Qp = g_Qh + (size_t)bh * 65536;
    const __half* Kp = g_Kh + (size_t)bh * 65536;
    const __half* Vtp = g_Vh + (size_t)bh * 65536;   // [64][1024]
    int mi32v = g_mask_i32;

    // stage 0: K, Vt, mask
    {
        char* st = smc;
        __half* Ks0 = (__half*)st;
        __half* Vt0 = (__half*)(st + FL_K_BYTES);
        unsigned char* Ms0 = (unsigned char*)(st + 2 * FL_K_BYTES);
#pragma unroll
        for (int l = 0; l < 2; l++) {
            int i = tid + l * 256;
            int r = i >> 3, c8 = (i & 7) * 8;
            cp_async16(&Ks0[r * FP + c8], Kp + (size_t)r * 64 + c8);
            cp_async16(&Vt0[r * FP + c8], Vtp + (size_t)r * 1024 + c8);
        }
        if (!mi32v) {
#pragma unroll
            for (int l = 0; l < 2; l++) {
                int i = tid + l * 256;
                int r = i >> 2, c16 = (i & 3) * 16;
                cp_async16(&Ms0[r * 64 + c16],
                           m8 + ((size_t)b << 20) + ((size_t)(sq0 + r) << 10) + c16);
            }
        }
        cp_commit();
    }

    // stage Q (plain stores), then fragments
#pragma unroll
    for (int l = 0; l < 4; l++) {
        int i = tid + l * 256;
        int r = i >> 3, c8 = (i & 7) * 8;
        *(uint4*)&Qs[r * FP + c8] = *(const uint4*)(Qp + (size_t)(sq0 + r) * 64 + c8);
    }
    __syncthreads();

    unsigned qa[4][4];
#pragma unroll
    for (int j = 0; j < 4; j++) {
        int e0 = j * 16;
        qa[j][0] = *(const unsigned*)&Qs[(rw0 + gid) * FP + e0 + 2 * tq];
        qa[j][1] = *(const unsigned*)&Qs[(rw0 + gid + 8) * FP + e0 + 2 * tq];
        qa[j][2] = *(const unsigned*)&Qs[(rw0 + gid) * FP + e0 + 8 + 2 * tq];
        qa[j][3] = *(const unsigned*)&Qs[(rw0 + gid + 8) * FP + e0 + 8 + 2 * tq];
    }

    float oacc[8][4];
#pragma unroll
    for (int n0 = 0; n0 < 8; n0++)
#pragma unroll
        for (int q = 0; q < 4; q++) oacc[n0][q] = 0.f;

    float lsum0 = 0.f, lsum1 = 0.f;
    const float scale = 0.03125f;  // 1/sqrt(1024)

    for (int t = 0; t < 16; ++t) {
        int sk0 = t * 64;
        cp_wait0();
        __syncthreads();

        if (t + 1 < 16) {
            int sk1 = sk0 + 64;
            char* st = smc + ((t + 1) & 1) * FL_STAGE_BYTES;
            __half* Ks2 = (__half*)st;
            __half* Vt2 = (__half*)(st + FL_K_BYTES);
            unsigned char* Ms2 = (unsigned char*)(st + 2 * FL_K_BYTES);
#pragma unroll
            for (int l = 0; l < 2; l++) {
                int i = tid + l * 256;
                int r = i >> 3, c8 = (i & 7) * 8;
                cp_async16(&Ks2[r * FP + c8], Kp + (size_t)(sk1 + r) * 64 + c8);
                cp_async16(&Vt2[r * FP + c8], Vtp + (size_t)r * 1024 + sk1 + c8);
            }
            if (!mi32v) {
#pragma unroll
                for (int l = 0; l < 2; l++) {
                    int i = tid + l * 256;
                    int r = i >> 2, c16 = (i & 3) * 16;
                    cp_async16(&Ms2[r * 64 + c16],
                               m8 + ((size_t)b << 20) + ((size_t)(sq0 + r) << 10) + sk1 + c16);
                }
            }
            cp_commit();
        }

        char* st = smc + (t & 1) * FL_STAGE_BYTES;
        const __half* Ks = (const __half*)st;
        const __half* Vts = (const __half*)(st + FL_K_BYTES);
        const unsigned char* Ms = (const unsigned char*)(st + 2 * FL_K_BYTES);

        // ---- S = Q K^T
        float sc[8][4];
#pragma unroll
        for (int n0 = 0; n0 < 8; n0++)
#pragma unroll
            for (int q = 0; q < 4; q++) sc[n0][q] = 0.f;
#pragma unroll
        for (int j = 0; j < 4; j++) {
            int e0 = j * 16;
#pragma unroll
            for (int n0 = 0; n0 < 8; n0++) {
                unsigned b0 = *(const unsigned*)&Ks[(8 * n0 + gid) * FP + e0 + 2 * tq];
                unsigned b1 = *(const unsigned*)&Ks[(8 * n0 + gid) * FP + e0 + 8 + 2 * tq];
                MMA16816(sc[n0], qa[j][0], qa[j][1], qa[j][2], qa[j][3], b0, b1);
            }
        }

        // ---- mask + exp + pack P (half2) in regs
        unsigned p0[8], p1[8];
#pragma unroll
        for (int n0 = 0; n0 < 8; n0++) {
            int c_lo = 8 * n0 + 2 * tq;
            int mv0, mv1, mv2, mv3;
            if (!mi32v) {
                unsigned short ms0 = *(const unsigned short*)&Ms[(rw0 + gid) * 64 + c_lo];
                unsigned short ms1 = *(const unsigned short*)&Ms[(rw0 + gid + 8) * 64 + c_lo];
                mv0 = ms0 & 0xFF; mv1 = ms0 >> 8;
                mv2 = ms1 & 0xFF; mv3 = ms1 >> 8;
            } else {
                const int* mr0 = m32 + ((size_t)b << 20) +
                                 ((size_t)(sq0 + rw0 + gid) << 10) + sk0 + c_lo;
                const int* mr1 = mr0 + (8 << 10);
                mv0 = mr0[0]; mv1 = mr0[1]; mv2 = mr1[0]; mv3 = mr1[1];
            }
            float e0v = mv0 ? 0.f : __expf(sc[n0][0] * scale);
            float e1v = mv1 ? 0.f : __expf(sc[n0][1] * scale);
            float e2v = mv2 ? 0.f : __expf(sc[n0][2] * scale);
            float e3v = mv3 ? 0.f : __expf(sc[n0][3] * scale);
            __half2 h01 = __floats2half2_rn(e0v, e1v);
            __half2 h23 = __floats2half2_rn(e2v, e3v);
            p0[n0] = *(unsigned*)&h01;
            p1[n0] = *(unsigned*)&h23;
            lsum0 += __half2float(__low2half(h01)) + __half2float(__high2half(h01));
            lsum1 += __half2float(__low2half(h23)) + __half2float(__high2half(h23));
        }

        // ---- O += P V
#pragma unroll
        for (int j = 0; j < 4; j++) {
            unsigned a0 = p0[2 * j], a1 = p1[2 * j];
            unsigned a2 = p0[2 * j + 1], a3 = p1[2 * j + 1];
#pragma unroll
            for (int n0 = 0; n0 < 8; n0++) {
                unsigned b0 = *(const unsigned*)&Vts[(8 * n0 + gid) * FP + 16 * j + 2 * tq];
                unsigned b1 = *(const unsigned*)&Vts[(8 * n0 + gid) * FP + 16 * j + 8 + 2 * tq];
                MMA16816(oacc[n0], a0, a1, a2, a3, b0, b1);
            }
        }
    }

    // ---- reduce l, normalize, store ctx (half)
    lsum0 += __shfl_xor_sync(0xFFFFFFFFu, lsum0, 1);
    lsum0 += __shfl_xor_sync(0xFFFFFFFFu, lsum0, 2);
    lsum1 += __shfl_xor_sync(0xFFFFFFFFu, lsum1, 1);
    lsum1 += __shfl_xor_sync(0xFFFFFFFFu, lsum1, 2);
    float inv0 = 1.0f / lsum0;
    float inv1 = 1.0f / lsum1;

    int rowg = sq0 + rw0 + gid;
    size_t base0 = (((size_t)b << 10) + rowg) * 1024 + (h << 6) + 2 * tq;
    size_t base1 = base0 + (size_t)8 * 1024;
#pragma unroll
    for (int n0 = 0; n0 < 8; n0++) {
        __half2 v0 = __floats2half2_rn(oacc[n0][0] * inv0, oacc[n0][1] * inv0);
        __half2 v1 = __floats2half2_rn(oacc[n0][2] * inv1, oacc[n0][3] * inv1);
        *(__half2*)&g_ctxh[base0 + 8 * n0] = v0;
        *(__half2*)&g_ctxh[base1 + 8 * n0] = v1;
    }
}

extern "C" void kernel_launch(void* const* d_in, const int* in_sizes, int n_in,
                              void* d_out, int out_size) {
    const float* x  = (const float*)d_in[0];
    const void*  mk = d_in[1];
    const float* Wq = (const float*)d_in[2];
    const float* bq = (const float*)d_in[3];
    const float* Wk = (const float*)d_in[4];
    const float* bk = (const float*)d_in[5];
    const float* Wv = (const float*)d_in[6];
    const float* bv = (const float*)d_in[7];
    const float* Wo = (const float*)d_in[8];
    const float* bo = (const float*)d_in[9];
    float* out = (float*)d_out;

    cudaFuncSetAttribute(flash_kernel, cudaFuncAttributeMaxDynamicSharedMemorySize,
                         FL_BYTES);
    cudaFuncSetAttribute(gemm_h, cudaFuncAttributeMaxDynamicSharedMemorySize,
                         G_SMEM_BYTES);

    detect_mask_kernel<<<1, 256>>>((const int*)mk);

    cvt_half_kernel<<<(ROWS * DMODEL / 8 + 255) / 256, 256>>>(x, 0, ROWS * DMODEL / 8);
    cvt_half_kernel<<<(1024 * 1024 / 8 + 255) / 256, 256>>>(Wo, 1, 1024 * 1024 / 8);
    repack_kernel<<<(3 * 1048576 + 255) / 256, 256>>>(Wq, bq, Wk, bk, Wv, bv);

    gemm_h<<<dim3(3072 / 128, ROWS / 128), 256, G_SMEM_BYTES>>>(
        nullptr, nullptr, 3072, 0);

    flash_kernel<<<dim3(SEQ / 128, BHN), 256, FL_BYTES>>>(
        (const unsigned char*)mk, (const int*)mk);

    gemm_h<<<dim3(1024 / 128, ROWS / 128), 256, G_SMEM_BYTES>>>(
        bo, out, 1024, 1);
}